// round 11
// baseline (speedup 1.0000x reference)
#include <cuda_runtime.h>
#include <cuda_bf16.h>
#include <math.h>

#define N_NODES   50000
#define N_EDGES   1600000
#define N_GRAPHS  128
#define EDGE_DIM  43
#define IN_DIM    35
#define HID       128

typedef unsigned long long ull_t;

// ---------------- scratch (device globals: sanctioned scratch mechanism) ----------------
__device__ float g_attr_s[(size_t)N_EDGES * EDGE_DIM];   // sorted edge_attr (275MB)
__device__ int   g_src_s[N_EDGES];
__device__ int   g_perm[N_EDGES];
__device__ int   g_src32[N_EDGES];
__device__ int   g_deg[N_NODES];
__device__ int   g_cursor[N_NODES];
__device__ int   g_flag_ei;      // 1 = edge_index is int64
__device__ int   g_flag_b;       // 1 = batch is int64
__device__ float g_A[(size_t)N_NODES * HID];             // per-node edge-side pre-activation
__device__ float g_hbuf[2][(size_t)N_NODES * HID];
__device__ float g_g1[(size_t)N_NODES * 64];
__device__ float g_g2[(size_t)N_NODES * 32];
__device__ float g_gate[N_NODES];
__device__ int   g_gcnt[N_GRAPHS];
__device__ int   g_gptr[N_GRAPHS + 1];
__device__ float g_emb[N_GRAPHS * HID];
__device__ float g_e2[N_GRAPHS * 256];
__device__ float g_o1[N_GRAPHS * 256];
__device__ float g_o2[N_GRAPHS * 128];
__device__ float g_o3[N_GRAPHS * 64];
__device__ float g_o4[N_GRAPHS * 4];

// ---------------- helpers ----------------
__device__ __forceinline__ float fast_tanh(float x) {
    float ax = fabsf(x);
    float t  = __expf(-2.0f * ax);            // <= 1, no overflow
    float r  = __fdividef(1.0f - t, 1.0f + t);
    return copysignf(r, x);
}

// packed fp32x2 FMA (FFMA2) — sm_100a+/sm_103a, only reachable via PTX
__device__ __forceinline__ void fma2(ull_t& d, ull_t a, ull_t b) {
    asm("fma.rn.f32x2 %0, %1, %2, %0;" : "+l"(d) : "l"(a), "l"(b));
}
__device__ __forceinline__ ull_t dup2(float x) {
    ull_t r; unsigned u = __float_as_uint(x);
    asm("mov.b64 %0, {%1, %1};" : "=l"(r) : "r"(u));
    return r;
}
__device__ __forceinline__ float f2lo(ull_t v){ return __uint_as_float((unsigned)(v & 0xffffffffull)); }
__device__ __forceinline__ float f2hi(ull_t v){ return __uint_as_float((unsigned)(v >> 32)); }

// ---------------- dtype probes + CSR build ----------------
__global__ void k_zero() {
    int i = blockIdx.x * blockDim.x + threadIdx.x;
    if (i < N_NODES)  g_deg[i]  = 0;
    if (i < N_GRAPHS) g_gcnt[i] = 0;
    if (i == 0) { g_flag_ei = 1; g_flag_b = 1; }
}

__global__ void k_detect_ei(const void* __restrict__ ei) {
    int e = blockIdx.x * blockDim.x + threadIdx.x;
    if (e < N_EDGES) {
        long long v = ((const long long*)ei)[e];
        if (v < 0 || v >= N_NODES) g_flag_ei = 0;
    }
}

__global__ void k_detect_b(const void* __restrict__ b) {
    int i = blockIdx.x * blockDim.x + threadIdx.x;
    if (i < N_NODES / 2) {
        long long v = ((const long long*)b)[i];
        if (v < 0 || v >= N_GRAPHS) g_flag_b = 0;
    }
}

__global__ void k_hist(const void* __restrict__ ei) {
    int e = blockIdx.x * blockDim.x + threadIdx.x;
    if (e < N_EDGES) {
        int s = g_flag_ei ? (int)((const long long*)ei)[e]
                          : ((const int*)ei)[e];
        if (s < 0) s = 0; else if (s >= N_NODES) s = N_NODES - 1;  // crash guard
        g_src32[e] = s;
        atomicAdd(&g_deg[s], 1);
    }
}

// exclusive scan of g_deg into g_cursor (single block, 1024 threads)
__global__ void k_scan() {
    __shared__ int sh[1024];
    __shared__ int carry;
    int t = threadIdx.x;
    if (t == 0) carry = 0;
    __syncthreads();
    for (int base = 0; base < N_NODES; base += 1024) {
        int v = (base + t < N_NODES) ? g_deg[base + t] : 0;
        sh[t] = v;
        __syncthreads();
        for (int off = 1; off < 1024; off <<= 1) {
            int add = (t >= off) ? sh[t - off] : 0;
            __syncthreads();
            sh[t] += add;
            __syncthreads();
        }
        if (base + t < N_NODES) g_cursor[base + t] = carry + sh[t] - v;
        __syncthreads();
        if (t == 0) carry += sh[1023];
        __syncthreads();
    }
}

__global__ void k_scatter() {
    int e = blockIdx.x * blockDim.x + threadIdx.x;
    if (e < N_EDGES) {
        int s = g_src32[e];
        int p = atomicAdd(&g_cursor[s], 1);
        if (p >= 0 && p < N_EDGES) {    // crash guard
            g_perm[p]  = e;
            g_src_s[p] = s;
        }
    }
}

__global__ void k_permute(const float* __restrict__ attr) {
    int idx = blockIdx.x * blockDim.x + threadIdx.x;
    if (idx < N_EDGES * EDGE_DIM) {
        int p = idx / EDGE_DIM;
        int c = idx - p * EDGE_DIM;
        g_attr_s[idx] = attr[(size_t)g_perm[p] * EDGE_DIM + c];
    }
}

// ---------------- generic tiled linear (f32x2): Y[M,N] = act(X[M,K] @ W[:,woff:woff+K].T + b) ----------------
// grid: (ceil(M/128), ceil(N/64)); block 256; micro-tile 8x4, acc packed along M
__global__ void __launch_bounds__(256) k_linear(
    const float* __restrict__ X, const float* __restrict__ W,
    const float* __restrict__ bias, float* __restrict__ Y,
    int M, int N, int K, int ldw, int woff, int act)
{
    __shared__ __align__(16) float Xs[16][132];
    __shared__ __align__(16) float Ws[16][68];
    int tid = threadIdx.x;
    int M0 = blockIdx.x * 128;
    int N0 = blockIdx.y * 64;
    int ty = tid >> 4, tx = tid & 15;
    ull_t acc2[4][4];
#pragma unroll
    for (int i = 0; i < 4; i++)
#pragma unroll
        for (int j = 0; j < 4; j++) acc2[i][j] = 0ull;

    for (int k0 = 0; k0 < K; k0 += 16) {
#pragma unroll
        for (int l = 0; l < 8; l++) {
            int idx = tid + l * 256;
            int m = idx >> 4, k = idx & 15;
            int gm = M0 + m, gk = k0 + k;
            Xs[k][m] = (gm < M && gk < K) ? X[(size_t)gm * K + gk] : 0.f;
        }
#pragma unroll
        for (int l = 0; l < 4; l++) {
            int idx = tid + l * 256;
            int n = idx >> 4, k = idx & 15;
            int gn = N0 + n, gk = k0 + k;
            Ws[k][n] = (gn < N && gk < K) ? W[gn * ldw + woff + gk] : 0.f;
        }
        __syncthreads();
#pragma unroll
        for (int kk = 0; kk < 16; kk++) {
            ulonglong2 xa = *(const ulonglong2*)&Xs[kk][ty * 8];       // pairs (m0,m1),(m2,m3)
            ulonglong2 xb = *(const ulonglong2*)&Xs[kk][ty * 8 + 4];   // pairs (m4,m5),(m6,m7)
            ull_t am[4] = {xa.x, xa.y, xb.x, xb.y};
            float4 wv = *(const float4*)&Ws[kk][tx * 4];
            ull_t wd[4] = {dup2(wv.x), dup2(wv.y), dup2(wv.z), dup2(wv.w)};
#pragma unroll
            for (int i = 0; i < 4; i++)
#pragma unroll
                for (int j = 0; j < 4; j++) fma2(acc2[i][j], am[i], wd[j]);
        }
        __syncthreads();
    }
#pragma unroll
    for (int j = 0; j < 4; j++) {
        int gn = N0 + tx * 4 + j;
        if (gn >= N) continue;
        float b = bias[gn];
#pragma unroll
        for (int i = 0; i < 4; i++) {
#pragma unroll
            for (int h = 0; h < 2; h++) {
                int gm = M0 + ty * 8 + i * 2 + h;
                if (gm >= M) continue;
                float v = (h ? f2hi(acc2[i][j]) : f2lo(acc2[i][j])) + b;
                if (act == 1)      v = fast_tanh(v);
                else if (act == 2) v = fmaxf(v, 0.f);
                Y[(size_t)gm * N + gn] = v;
            }
        }
    }
}

// ---------------- fused edge GEMM (f32x2) + tanh + segment scatter ----------------
// out[src[e]] += tanh(A[src[e]] + attr_sorted[e] @ We.T), 128-edge x 128-channel tile
// lane map: lx = lane&7 -> channel quad (conflict-free Ws LDS.128),
//           ly = lane>>3, warp w -> 4 sorted edges (broadcast As LDS.128)
// thread: 4 edges x 16 channels (quads at c0, c0+32, c0+64, c0+96); acc packed along channels
__global__ void __launch_bounds__(256) k_edge_conv(
    const float* __restrict__ W, int ldw, int woff,
    const float* __restrict__ A, float* __restrict__ out)
{
    __shared__ __align__(16) float As[EDGE_DIM][128];   // [k][edge]
    __shared__ __align__(16) float Ws[EDGE_DIM][128];   // [k][channel]
    __shared__ int ssrc[128];
    int tid = threadIdx.x;
    int t0  = blockIdx.x * 128;                         // N_EDGES % 128 == 0
    const float* attrBase = g_attr_s + (size_t)t0 * EDGE_DIM;
    for (int idx = tid; idx < 128 * EDGE_DIM; idx += 256) {
        int e = idx / EDGE_DIM;
        int k = idx - e * EDGE_DIM;
        As[k][e] = attrBase[idx];
    }
    for (int idx = tid; idx < 128 * EDGE_DIM; idx += 256) {
        int c = idx / EDGE_DIM;
        int k = idx - c * EDGE_DIM;
        Ws[k][c] = W[c * ldw + woff + k];
    }
    if (tid < 128) ssrc[tid] = g_src_s[t0 + tid];
    __syncthreads();

    int l  = tid & 31, w = tid >> 5;
    int lx = l & 7,  ly = l >> 3;
    int e0 = w * 16 + ly * 4;
    int c0 = lx * 4;

    ull_t acc2[4][8];
#pragma unroll
    for (int i = 0; i < 4; i++)
#pragma unroll
        for (int p = 0; p < 8; p++) acc2[i][p] = 0ull;

    for (int k = 0; k < EDGE_DIM; k++) {
        float4 av = *(const float4*)&As[k][e0];                    // broadcast within phase
        ull_t a[4] = {dup2(av.x), dup2(av.y), dup2(av.z), dup2(av.w)};
        ulonglong2 b0 = *(const ulonglong2*)&Ws[k][c0];            // conflict-free 128B/phase
        ulonglong2 b1 = *(const ulonglong2*)&Ws[k][c0 + 32];
        ulonglong2 b2 = *(const ulonglong2*)&Ws[k][c0 + 64];
        ulonglong2 b3 = *(const ulonglong2*)&Ws[k][c0 + 96];
        ull_t b[8] = {b0.x, b0.y, b1.x, b1.y, b2.x, b2.y, b3.x, b3.y};
#pragma unroll
        for (int i = 0; i < 4; i++)
#pragma unroll
            for (int p = 0; p < 8; p++) fma2(acc2[i][p], a[i], b[p]);
    }

    // epilogue: run-length segment reduce over 4 sorted edges
    float part[16], areg[16];
    int prev = -1;
#pragma unroll
    for (int i = 0; i < 4; i++) {
        int s = ssrc[e0 + i];
        if (s != prev) {
            if (prev >= 0) {
                float* op = out + (size_t)prev * HID;
#pragma unroll
                for (int q = 0; q < 4; q++)
#pragma unroll
                    for (int j = 0; j < 4; j++)
                        atomicAdd(op + q * 32 + c0 + j, part[q * 4 + j]);
            }
            prev = s;
            const float* Ap = A + (size_t)s * HID;
#pragma unroll
            for (int q = 0; q < 4; q++) {
                float4 v = *(const float4*)(Ap + q * 32 + c0);
                areg[q * 4 + 0] = v.x; areg[q * 4 + 1] = v.y;
                areg[q * 4 + 2] = v.z; areg[q * 4 + 3] = v.w;
            }
#pragma unroll
            for (int j = 0; j < 16; j++) part[j] = 0.f;
        }
#pragma unroll
        for (int q = 0; q < 4; q++) {
#pragma unroll
            for (int h = 0; h < 2; h++) {
                ull_t v = acc2[i][q * 2 + h];
                part[q * 4 + h * 2 + 0] += fast_tanh(f2lo(v) + areg[q * 4 + h * 2 + 0]);
                part[q * 4 + h * 2 + 1] += fast_tanh(f2hi(v) + areg[q * 4 + h * 2 + 1]);
            }
        }
    }
    {
        float* op = out + (size_t)prev * HID;
#pragma unroll
        for (int q = 0; q < 4; q++)
#pragma unroll
            for (int j = 0; j < 4; j++)
                atomicAdd(op + q * 32 + c0 + j, part[q * 4 + j]);
    }
}

// ---------------- graph segmentation + attention readout ----------------
__global__ void k_gcnt(const void* __restrict__ batch) {
    int n = blockIdx.x * blockDim.x + threadIdx.x;
    if (n < N_NODES) {
        int g = g_flag_b ? (int)((const long long*)batch)[n]
                         : ((const int*)batch)[n];
        if (g < 0) g = 0; else if (g >= N_GRAPHS) g = N_GRAPHS - 1;  // crash guard
        atomicAdd(&g_gcnt[g], 1);
    }
}

__global__ void k_gscan() {
    if (threadIdx.x == 0 && blockIdx.x == 0) {
        int run = 0;
        g_gptr[0] = 0;
        for (int g = 0; g < N_GRAPHS; g++) { run += g_gcnt[g]; g_gptr[g + 1] = run; }
    }
}

// one block (128 threads) per graph: segment softmax + weighted sum
__global__ void k_attn(const float* __restrict__ h, float* __restrict__ attout) {
    int g = blockIdx.x, t = threadIdx.x;
    int lo = g_gptr[g], hi = g_gptr[g + 1];
    __shared__ float red[128];
    float m = -1e30f;
    for (int n = lo + t; n < hi; n += 128) m = fmaxf(m, g_gate[n]);
    red[t] = m; __syncthreads();
    for (int s = 64; s > 0; s >>= 1) { if (t < s) red[t] = fmaxf(red[t], red[t + s]); __syncthreads(); }
    m = red[0]; __syncthreads();
    float sum = 0.f;
    for (int n = lo + t; n < hi; n += 128) sum += __expf(g_gate[n] - m);
    red[t] = sum; __syncthreads();
    for (int s = 64; s > 0; s >>= 1) { if (t < s) red[t] += red[t + s]; __syncthreads(); }
    float inv = 1.0f / (red[0] + 1e-16f);
    for (int n = lo + t; n < hi; n += 128) attout[n] = __expf(g_gate[n] - m) * inv;
    float a0 = 0.f, a1 = 0.f, a2 = 0.f, a3 = 0.f;
    int n = lo;
    for (; n + 3 < hi; n += 4) {
        float w0 = __expf(g_gate[n]     - m) * inv;
        float w1 = __expf(g_gate[n + 1] - m) * inv;
        float w2 = __expf(g_gate[n + 2] - m) * inv;
        float w3 = __expf(g_gate[n + 3] - m) * inv;
        a0 += w0 * h[(size_t)n * HID + t];
        a1 += w1 * h[(size_t)(n + 1) * HID + t];
        a2 += w2 * h[(size_t)(n + 2) * HID + t];
        a3 += w3 * h[(size_t)(n + 3) * HID + t];
    }
    for (; n < hi; n++) {
        a0 += __expf(g_gate[n] - m) * inv * h[(size_t)n * HID + t];
    }
    g_emb[g * HID + t] = (a0 + a1) + (a2 + a3);
}

__global__ void k_concat(const float* __restrict__ us, const float* __restrict__ ud) {
    int idx = blockIdx.x * blockDim.x + threadIdx.x;
    if (idx < N_GRAPHS * 256) {
        int g = idx >> 8, c = idx & 255;
        float v;
        if (c < 128)      v = g_emb[g * 128 + c];
        else if (c < 192) v = us[g * 64 + (c - 128)];
        else              v = ud[g * 64 + (c - 192)];
        g_e2[idx] = v;
    }
}

__global__ void k_out(float* __restrict__ out) {
    int g = threadIdx.x;
    if (g < N_GRAPHS) {
        float s = 0.f;
#pragma unroll
        for (int j = 0; j < 4; j++) { float v = g_o4[g * 4 + j]; out[g * 5 + j] = v; s += v; }
        out[g * 5 + 4] = s;
    }
}

// ---------------- driver ----------------
extern "C" void kernel_launch(void* const* d_in, const int* in_sizes, int n_in,
                              void* d_out, int out_size)
{
    const float* x        = (const float*)d_in[0];
    const float* edge_attr= (const float*)d_in[1];
    const float* u_soap   = (const float*)d_in[2];
    const float* u_dimer  = (const float*)d_in[3];
    const float* W1n = (const float*)d_in[4];  const float* b1n = (const float*)d_in[5];
    const float* W1r = (const float*)d_in[6];  const float* b1r = (const float*)d_in[7];
    const float* W2n = (const float*)d_in[8];  const float* b2n = (const float*)d_in[9];
    const float* W2r = (const float*)d_in[10]; const float* b2r = (const float*)d_in[11];
    const float* W3n = (const float*)d_in[12]; const float* b3n = (const float*)d_in[13];
    const float* W3r = (const float*)d_in[14]; const float* b3r = (const float*)d_in[15];
    const float* Wg1 = (const float*)d_in[16]; const float* bg1 = (const float*)d_in[17];
    const float* Wg2 = (const float*)d_in[18]; const float* bg2 = (const float*)d_in[19];
    const float* Wg3 = (const float*)d_in[20]; const float* bg3 = (const float*)d_in[21];
    const float* Wl1 = (const float*)d_in[22]; const float* bl1 = (const float*)d_in[23];
    const float* Wl2 = (const float*)d_in[24]; const float* bl2 = (const float*)d_in[25];
    const float* Wl3 = (const float*)d_in[26]; const float* bl3 = (const float*)d_in[27];
    const float* Wl  = (const float*)d_in[28]; const float* bl  = (const float*)d_in[29];
    const void*  edge_index = d_in[30];
    const void*  batch      = d_in[31];
    float* out = (float*)d_out;

    float *pA, *ph, *pg1, *pg2, *pgate, *pe2, *po1, *po2, *po3, *po4;
    cudaGetSymbolAddress((void**)&pA,    g_A);
    cudaGetSymbolAddress((void**)&ph,    g_hbuf);
    cudaGetSymbolAddress((void**)&pg1,   g_g1);
    cudaGetSymbolAddress((void**)&pg2,   g_g2);
    cudaGetSymbolAddress((void**)&pgate, g_gate);
    cudaGetSymbolAddress((void**)&pe2,   g_e2);
    cudaGetSymbolAddress((void**)&po1,   g_o1);
    cudaGetSymbolAddress((void**)&po2,   g_o2);
    cudaGetSymbolAddress((void**)&po3,   g_o3);
    cudaGetSymbolAddress((void**)&po4,   g_o4);
    float* ph0 = ph;
    float* ph1 = ph + (size_t)N_NODES * HID;

    const int NB_M = (N_NODES + 127) / 128;            // 391
    const int EB   = (N_EDGES + 127) / 128;            // 12500

    // dtype probes + CSR build
    k_zero     <<<(N_NODES + 255) / 256, 256>>>();
    k_detect_ei<<<(N_EDGES + 255) / 256, 256>>>(edge_index);
    k_detect_b <<<(N_NODES / 2 + 255) / 256, 256>>>(batch);
    k_hist     <<<(N_EDGES + 255) / 256, 256>>>(edge_index);
    k_scan     <<<1, 1024>>>();
    k_scatter  <<<(N_EDGES + 255) / 256, 256>>>();
    k_permute  <<<(N_EDGES * EDGE_DIM + 255) / 256, 256>>>(edge_attr);

    // layer 1 (K = IN_DIM)
    k_linear<<<dim3(NB_M, 2), 256>>>(x,   W1n, b1n, pA,  N_NODES, 128, IN_DIM, IN_DIM + EDGE_DIM, 0, 0);
    k_linear<<<dim3(NB_M, 2), 256>>>(x,   W1r, b1r, ph0, N_NODES, 128, IN_DIM, IN_DIM,            0, 1);
    k_edge_conv<<<EB, 256>>>(W1n, IN_DIM + EDGE_DIM, IN_DIM, pA, ph0);

    // layer 2 (K = HID)
    k_linear<<<dim3(NB_M, 2), 256>>>(ph0, W2n, b2n, pA,  N_NODES, 128, HID, HID + EDGE_DIM, 0, 0);
    k_linear<<<dim3(NB_M, 2), 256>>>(ph0, W2r, b2r, ph1, N_NODES, 128, HID, HID,            0, 1);
    k_edge_conv<<<EB, 256>>>(W2n, HID + EDGE_DIM, HID, pA, ph1);

    // layer 3
    k_linear<<<dim3(NB_M, 2), 256>>>(ph1, W3n, b3n, pA,  N_NODES, 128, HID, HID + EDGE_DIM, 0, 0);
    k_linear<<<dim3(NB_M, 2), 256>>>(ph1, W3r, b3r, ph0, N_NODES, 128, HID, HID,            0, 1);
    k_edge_conv<<<EB, 256>>>(W3n, HID + EDGE_DIM, HID, pA, ph0);
    // h3 = ph0

    // gate MLP
    k_linear<<<dim3(NB_M, 1), 256>>>(ph0, Wg1, bg1, pg1,   N_NODES, 64, 128, 128, 0, 2);
    k_linear<<<dim3(NB_M, 1), 256>>>(pg1, Wg2, bg2, pg2,   N_NODES, 32, 64,  64,  0, 2);
    k_linear<<<dim3(NB_M, 1), 256>>>(pg2, Wg3, bg3, pgate, N_NODES, 1,  32,  32,  0, 0);

    // graph segments + attention readout (att written after the [G,5] preds)
    k_gcnt <<<(N_NODES + 255) / 256, 256>>>(batch);
    k_gscan<<<1, 32>>>();
    k_attn <<<N_GRAPHS, 128>>>(ph0, out + N_GRAPHS * 5);

    // head MLP
    k_concat<<<(N_GRAPHS * 256 + 255) / 256, 256>>>(u_soap, u_dimer);
    k_linear<<<dim3(1, 4), 256>>>(pe2, Wl1, bl1, po1, N_GRAPHS, 256, 256, 256, 0, 2);
    k_linear<<<dim3(1, 2), 256>>>(po1, Wl2, bl2, po2, N_GRAPHS, 128, 256, 256, 0, 2);
    k_linear<<<dim3(1, 1), 256>>>(po2, Wl3, bl3, po3, N_GRAPHS, 64,  128, 128, 0, 2);
    k_linear<<<dim3(1, 1), 256>>>(po3, Wl,  bl,  po4, N_GRAPHS, 4,   64,  64,  0, 0);
    k_out<<<1, 128>>>(out);
}

// round 12
// speedup vs baseline: 1.3739x; 1.3739x over previous
#include <cuda_runtime.h>
#include <cuda_bf16.h>
#include <math.h>

#define N_NODES   50000
#define N_EDGES   1600000
#define N_GRAPHS  128
#define EDGE_DIM  43
#define IN_DIM    35
#define HID       128

// ---------------- scratch (device globals: sanctioned scratch mechanism) ----------------
__device__ float g_attr_s[(size_t)N_EDGES * EDGE_DIM];   // sorted edge_attr (275MB)
__device__ int   g_src_s[N_EDGES];
__device__ int   g_perm[N_EDGES];
__device__ int   g_src32[N_EDGES];
__device__ int   g_deg[N_NODES];
__device__ int   g_cursor[N_NODES];
__device__ int   g_flag_ei;      // 1 = edge_index is int64
__device__ int   g_flag_b;       // 1 = batch is int64
__device__ float g_A[(size_t)N_NODES * HID];             // per-node edge-side pre-activation
__device__ float g_hbuf[2][(size_t)N_NODES * HID];
__device__ float g_g1[(size_t)N_NODES * 64];
__device__ float g_g2[(size_t)N_NODES * 32];
__device__ float g_gate[N_NODES];
__device__ int   g_gcnt[N_GRAPHS];
__device__ int   g_gptr[N_GRAPHS + 1];
__device__ float g_emb[N_GRAPHS * HID];
__device__ float g_e2[N_GRAPHS * 256];
__device__ float g_o1[N_GRAPHS * 256];
__device__ float g_o2[N_GRAPHS * 128];
__device__ float g_o3[N_GRAPHS * 64];
__device__ float g_o4[N_GRAPHS * 4];

// ---------------- helpers ----------------
__device__ __forceinline__ float fast_tanh(float x) {
    float ax = fabsf(x);
    float t  = __expf(-2.0f * ax);            // <= 1, no overflow
    float r  = __fdividef(1.0f - t, 1.0f + t);
    return copysignf(r, x);
}

// ---------------- dtype probes + CSR build ----------------
__global__ void k_zero() {
    int i = blockIdx.x * blockDim.x + threadIdx.x;
    if (i < N_NODES)  g_deg[i]  = 0;
    if (i < N_GRAPHS) g_gcnt[i] = 0;
    if (i == 0) { g_flag_ei = 1; g_flag_b = 1; }
}

__global__ void k_detect_ei(const void* __restrict__ ei) {
    int e = blockIdx.x * blockDim.x + threadIdx.x;
    if (e < N_EDGES) {
        long long v = ((const long long*)ei)[e];
        if (v < 0 || v >= N_NODES) g_flag_ei = 0;
    }
}

__global__ void k_detect_b(const void* __restrict__ b) {
    int i = blockIdx.x * blockDim.x + threadIdx.x;
    if (i < N_NODES / 2) {
        long long v = ((const long long*)b)[i];
        if (v < 0 || v >= N_GRAPHS) g_flag_b = 0;
    }
}

__global__ void k_hist(const void* __restrict__ ei) {
    int e = blockIdx.x * blockDim.x + threadIdx.x;
    if (e < N_EDGES) {
        int s = g_flag_ei ? (int)((const long long*)ei)[e]
                          : ((const int*)ei)[e];
        if (s < 0) s = 0; else if (s >= N_NODES) s = N_NODES - 1;  // crash guard
        g_src32[e] = s;
        atomicAdd(&g_deg[s], 1);
    }
}

// exclusive scan of g_deg into g_cursor (single block, 1024 threads)
__global__ void k_scan() {
    __shared__ int sh[1024];
    __shared__ int carry;
    int t = threadIdx.x;
    if (t == 0) carry = 0;
    __syncthreads();
    for (int base = 0; base < N_NODES; base += 1024) {
        int v = (base + t < N_NODES) ? g_deg[base + t] : 0;
        sh[t] = v;
        __syncthreads();
        for (int off = 1; off < 1024; off <<= 1) {
            int add = (t >= off) ? sh[t - off] : 0;
            __syncthreads();
            sh[t] += add;
            __syncthreads();
        }
        if (base + t < N_NODES) g_cursor[base + t] = carry + sh[t] - v;
        __syncthreads();
        if (t == 0) carry += sh[1023];
        __syncthreads();
    }
}

__global__ void k_scatter() {
    int e = blockIdx.x * blockDim.x + threadIdx.x;
    if (e < N_EDGES) {
        int s = g_src32[e];
        int p = atomicAdd(&g_cursor[s], 1);
        if (p >= 0 && p < N_EDGES) {    // crash guard
            g_perm[p]  = e;
            g_src_s[p] = s;
        }
    }
}

__global__ void k_permute(const float* __restrict__ attr) {
    int idx = blockIdx.x * blockDim.x + threadIdx.x;
    if (idx < N_EDGES * EDGE_DIM) {
        int p = idx / EDGE_DIM;
        int c = idx - p * EDGE_DIM;
        g_attr_s[idx] = attr[(size_t)g_perm[p] * EDGE_DIM + c];
    }
}

// ---------------- generic tiled linear: Y[M,N] = act(X[M,K] @ W[:, woff:woff+K].T + b) ----------------
// grid: (ceil(M/128), ceil(N/64)); block 256; micro-tile 8x4   (proven R5 version)
__global__ void k_linear(const float* __restrict__ X, const float* __restrict__ W,
                         const float* __restrict__ bias, float* __restrict__ Y,
                         int M, int N, int K, int ldw, int woff, int act)
{
    __shared__ __align__(16) float Xs[16][132];
    __shared__ __align__(16) float Ws[16][68];
    int tid = threadIdx.x;
    int M0 = blockIdx.x * 128;
    int N0 = blockIdx.y * 64;
    int ty = tid >> 4, tx = tid & 15;
    float acc[8][4];
#pragma unroll
    for (int i = 0; i < 8; i++)
#pragma unroll
        for (int j = 0; j < 4; j++) acc[i][j] = 0.f;

    for (int k0 = 0; k0 < K; k0 += 16) {
#pragma unroll
        for (int l = 0; l < 8; l++) {
            int idx = tid + l * 256;
            int m = idx >> 4, k = idx & 15;
            int gm = M0 + m, gk = k0 + k;
            Xs[k][m] = (gm < M && gk < K) ? X[(size_t)gm * K + gk] : 0.f;
        }
#pragma unroll
        for (int l = 0; l < 4; l++) {
            int idx = tid + l * 256;
            int n = idx >> 4, k = idx & 15;
            int gn = N0 + n, gk = k0 + k;
            Ws[k][n] = (gn < N && gk < K) ? W[gn * ldw + woff + gk] : 0.f;
        }
        __syncthreads();
#pragma unroll
        for (int kk = 0; kk < 16; kk++) {
            float4 a0 = *(const float4*)&Xs[kk][ty * 8];
            float4 a1 = *(const float4*)&Xs[kk][ty * 8 + 4];
            float4 w  = *(const float4*)&Ws[kk][tx * 4];
            float a[8] = {a0.x, a0.y, a0.z, a0.w, a1.x, a1.y, a1.z, a1.w};
            float wv[4] = {w.x, w.y, w.z, w.w};
#pragma unroll
            for (int i = 0; i < 8; i++)
#pragma unroll
                for (int j = 0; j < 4; j++) acc[i][j] += a[i] * wv[j];
        }
        __syncthreads();
    }
#pragma unroll
    for (int j = 0; j < 4; j++) {
        int gn = N0 + tx * 4 + j;
        if (gn >= N) continue;
        float b = bias[gn];
#pragma unroll
        for (int i = 0; i < 8; i++) {
            int gm = M0 + ty * 8 + i;
            if (gm >= M) continue;
            float v = acc[i][j] + b;
            if (act == 1)      v = fast_tanh(v);
            else if (act == 2) v = fmaxf(v, 0.f);
            Y[(size_t)gm * N + gn] = v;
        }
    }
}

// ---------------- fused edge GEMM + tanh + segment scatter (scalar FFMA, conflict-free smem) ----------------
// out[src[e]] += tanh(A[src[e]] + attr_sorted[e] @ We.T), 128-edge x 128-channel tile
// lane map: lx = lane&7 -> channel quad (Ws quads at c0,c0+32,c0+64,c0+96: 8 lanes x 16B = 128B/phase, conflict-free)
//           ly = lane>>3, warp w -> 4 sorted edges (As load is broadcast within phase)
__global__ void __launch_bounds__(256) k_edge_conv(
    const float* __restrict__ W, int ldw, int woff,
    const float* __restrict__ A, float* __restrict__ out)
{
    __shared__ __align__(16) float As[EDGE_DIM][128];   // [k][edge]
    __shared__ __align__(16) float Ws[EDGE_DIM][128];   // [k][channel]
    __shared__ int ssrc[128];
    int tid = threadIdx.x;
    int t0  = blockIdx.x * 128;                         // N_EDGES % 128 == 0
    const float* attrBase = g_attr_s + (size_t)t0 * EDGE_DIM;
    for (int idx = tid; idx < 128 * EDGE_DIM; idx += 256) {
        int e = idx / EDGE_DIM;
        int k = idx - e * EDGE_DIM;
        As[k][e] = attrBase[idx];
    }
    for (int idx = tid; idx < 128 * EDGE_DIM; idx += 256) {
        int c = idx / EDGE_DIM;
        int k = idx - c * EDGE_DIM;
        Ws[k][c] = W[c * ldw + woff + k];
    }
    if (tid < 128) ssrc[tid] = g_src_s[t0 + tid];
    __syncthreads();

    int l  = tid & 31, w = tid >> 5;
    int lx = l & 7,  ly = l >> 3;
    int e0 = w * 16 + ly * 4;       // 4 consecutive sorted edges
    int c0 = lx * 4;                // channel quads at c0 + {0,32,64,96}

    float acc[4][16];
#pragma unroll
    for (int i = 0; i < 4; i++)
#pragma unroll
        for (int j = 0; j < 16; j++) acc[i][j] = 0.f;

    for (int k = 0; k < EDGE_DIM; k++) {
        float4 av = *(const float4*)&As[k][e0];                    // broadcast within phase
        float a[4] = {av.x, av.y, av.z, av.w};
        float4 b0 = *(const float4*)&Ws[k][c0];                    // conflict-free phases
        float4 b1 = *(const float4*)&Ws[k][c0 + 32];
        float4 b2 = *(const float4*)&Ws[k][c0 + 64];
        float4 b3 = *(const float4*)&Ws[k][c0 + 96];
        float b[16] = {b0.x, b0.y, b0.z, b0.w, b1.x, b1.y, b1.z, b1.w,
                       b2.x, b2.y, b2.z, b2.w, b3.x, b3.y, b3.z, b3.w};
#pragma unroll
        for (int i = 0; i < 4; i++)
#pragma unroll
            for (int j = 0; j < 16; j++) acc[i][j] += a[i] * b[j];
    }

    // epilogue: run-length segment reduce over 4 sorted edges
    float part[16], areg[16];
    int prev = -1;
#pragma unroll
    for (int i = 0; i < 4; i++) {
        int s = ssrc[e0 + i];
        if (s != prev) {
            if (prev >= 0) {
                float* op = out + (size_t)prev * HID;
#pragma unroll
                for (int q = 0; q < 4; q++)
#pragma unroll
                    for (int j = 0; j < 4; j++)
                        atomicAdd(op + q * 32 + c0 + j, part[q * 4 + j]);
            }
            prev = s;
            const float* Ap = A + (size_t)s * HID;
#pragma unroll
            for (int q = 0; q < 4; q++) {
                float4 v = *(const float4*)(Ap + q * 32 + c0);
                areg[q * 4 + 0] = v.x; areg[q * 4 + 1] = v.y;
                areg[q * 4 + 2] = v.z; areg[q * 4 + 3] = v.w;
            }
#pragma unroll
            for (int j = 0; j < 16; j++) part[j] = 0.f;
        }
#pragma unroll
        for (int j = 0; j < 16; j++)
            part[j] += fast_tanh(acc[i][j] + areg[j]);
    }
    {
        float* op = out + (size_t)prev * HID;
#pragma unroll
        for (int q = 0; q < 4; q++)
#pragma unroll
            for (int j = 0; j < 4; j++)
                atomicAdd(op + q * 32 + c0 + j, part[q * 4 + j]);
    }
}

// ---------------- graph segmentation + attention readout ----------------
__global__ void k_gcnt(const void* __restrict__ batch) {
    int n = blockIdx.x * blockDim.x + threadIdx.x;
    if (n < N_NODES) {
        int g = g_flag_b ? (int)((const long long*)batch)[n]
                         : ((const int*)batch)[n];
        if (g < 0) g = 0; else if (g >= N_GRAPHS) g = N_GRAPHS - 1;  // crash guard
        atomicAdd(&g_gcnt[g], 1);
    }
}

__global__ void k_gscan() {
    if (threadIdx.x == 0 && blockIdx.x == 0) {
        int run = 0;
        g_gptr[0] = 0;
        for (int g = 0; g < N_GRAPHS; g++) { run += g_gcnt[g]; g_gptr[g + 1] = run; }
    }
}

// one block (128 threads) per graph: segment softmax + weighted sum
__global__ void k_attn(const float* __restrict__ h, float* __restrict__ attout) {
    int g = blockIdx.x, t = threadIdx.x;
    int lo = g_gptr[g], hi = g_gptr[g + 1];
    __shared__ float red[128];
    float m = -1e30f;
    for (int n = lo + t; n < hi; n += 128) m = fmaxf(m, g_gate[n]);
    red[t] = m; __syncthreads();
    for (int s = 64; s > 0; s >>= 1) { if (t < s) red[t] = fmaxf(red[t], red[t + s]); __syncthreads(); }
    m = red[0]; __syncthreads();
    float sum = 0.f;
    for (int n = lo + t; n < hi; n += 128) sum += __expf(g_gate[n] - m);
    red[t] = sum; __syncthreads();
    for (int s = 64; s > 0; s >>= 1) { if (t < s) red[t] += red[t + s]; __syncthreads(); }
    float inv = 1.0f / (red[0] + 1e-16f);
    for (int n = lo + t; n < hi; n += 128) attout[n] = __expf(g_gate[n] - m) * inv;
    float a0 = 0.f, a1 = 0.f, a2 = 0.f, a3 = 0.f;
    int n = lo;
    for (; n + 3 < hi; n += 4) {
        float w0 = __expf(g_gate[n]     - m) * inv;
        float w1 = __expf(g_gate[n + 1] - m) * inv;
        float w2 = __expf(g_gate[n + 2] - m) * inv;
        float w3 = __expf(g_gate[n + 3] - m) * inv;
        a0 += w0 * h[(size_t)n * HID + t];
        a1 += w1 * h[(size_t)(n + 1) * HID + t];
        a2 += w2 * h[(size_t)(n + 2) * HID + t];
        a3 += w3 * h[(size_t)(n + 3) * HID + t];
    }
    for (; n < hi; n++) {
        a0 += __expf(g_gate[n] - m) * inv * h[(size_t)n * HID + t];
    }
    g_emb[g * HID + t] = (a0 + a1) + (a2 + a3);
}

__global__ void k_concat(const float* __restrict__ us, const float* __restrict__ ud) {
    int idx = blockIdx.x * blockDim.x + threadIdx.x;
    if (idx < N_GRAPHS * 256) {
        int g = idx >> 8, c = idx & 255;
        float v;
        if (c < 128)      v = g_emb[g * 128 + c];
        else if (c < 192) v = us[g * 64 + (c - 128)];
        else              v = ud[g * 64 + (c - 192)];
        g_e2[idx] = v;
    }
}

__global__ void k_out(float* __restrict__ out) {
    int g = threadIdx.x;
    if (g < N_GRAPHS) {
        float s = 0.f;
#pragma unroll
        for (int j = 0; j < 4; j++) { float v = g_o4[g * 4 + j]; out[g * 5 + j] = v; s += v; }
        out[g * 5 + 4] = s;
    }
}

// ---------------- driver ----------------
extern "C" void kernel_launch(void* const* d_in, const int* in_sizes, int n_in,
                              void* d_out, int out_size)
{
    const float* x        = (const float*)d_in[0];
    const float* edge_attr= (const float*)d_in[1];
    const float* u_soap   = (const float*)d_in[2];
    const float* u_dimer  = (const float*)d_in[3];
    const float* W1n = (const float*)d_in[4];  const float* b1n = (const float*)d_in[5];
    const float* W1r = (const float*)d_in[6];  const float* b1r = (const float*)d_in[7];
    const float* W2n = (const float*)d_in[8];  const float* b2n = (const float*)d_in[9];
    const float* W2r = (const float*)d_in[10]; const float* b2r = (const float*)d_in[11];
    const float* W3n = (const float*)d_in[12]; const float* b3n = (const float*)d_in[13];
    const float* W3r = (const float*)d_in[14]; const float* b3r = (const float*)d_in[15];
    const float* Wg1 = (const float*)d_in[16]; const float* bg1 = (const float*)d_in[17];
    const float* Wg2 = (const float*)d_in[18]; const float* bg2 = (const float*)d_in[19];
    const float* Wg3 = (const float*)d_in[20]; const float* bg3 = (const float*)d_in[21];
    const float* Wl1 = (const float*)d_in[22]; const float* bl1 = (const float*)d_in[23];
    const float* Wl2 = (const float*)d_in[24]; const float* bl2 = (const float*)d_in[25];
    const float* Wl3 = (const float*)d_in[26]; const float* bl3 = (const float*)d_in[27];
    const float* Wl  = (const float*)d_in[28]; const float* bl  = (const float*)d_in[29];
    const void*  edge_index = d_in[30];
    const void*  batch      = d_in[31];
    float* out = (float*)d_out;

    float *pA, *ph, *pg1, *pg2, *pgate, *pe2, *po1, *po2, *po3, *po4;
    cudaGetSymbolAddress((void**)&pA,    g_A);
    cudaGetSymbolAddress((void**)&ph,    g_hbuf);
    cudaGetSymbolAddress((void**)&pg1,   g_g1);
    cudaGetSymbolAddress((void**)&pg2,   g_g2);
    cudaGetSymbolAddress((void**)&pgate, g_gate);
    cudaGetSymbolAddress((void**)&pe2,   g_e2);
    cudaGetSymbolAddress((void**)&po1,   g_o1);
    cudaGetSymbolAddress((void**)&po2,   g_o2);
    cudaGetSymbolAddress((void**)&po3,   g_o3);
    cudaGetSymbolAddress((void**)&po4,   g_o4);
    float* ph0 = ph;
    float* ph1 = ph + (size_t)N_NODES * HID;

    const int NB_M = (N_NODES + 127) / 128;            // 391
    const int EB   = (N_EDGES + 127) / 128;            // 12500

    // dtype probes + CSR build
    k_zero     <<<(N_NODES + 255) / 256, 256>>>();
    k_detect_ei<<<(N_EDGES + 255) / 256, 256>>>(edge_index);
    k_detect_b <<<(N_NODES / 2 + 255) / 256, 256>>>(batch);
    k_hist     <<<(N_EDGES + 255) / 256, 256>>>(edge_index);
    k_scan     <<<1, 1024>>>();
    k_scatter  <<<(N_EDGES + 255) / 256, 256>>>();
    k_permute  <<<(N_EDGES * EDGE_DIM + 255) / 256, 256>>>(edge_attr);

    // layer 1 (K = IN_DIM)
    k_linear<<<dim3(NB_M, 2), 256>>>(x,   W1n, b1n, pA,  N_NODES, 128, IN_DIM, IN_DIM + EDGE_DIM, 0, 0);
    k_linear<<<dim3(NB_M, 2), 256>>>(x,   W1r, b1r, ph0, N_NODES, 128, IN_DIM, IN_DIM,            0, 1);
    k_edge_conv<<<EB, 256>>>(W1n, IN_DIM + EDGE_DIM, IN_DIM, pA, ph0);

    // layer 2 (K = HID)
    k_linear<<<dim3(NB_M, 2), 256>>>(ph0, W2n, b2n, pA,  N_NODES, 128, HID, HID + EDGE_DIM, 0, 0);
    k_linear<<<dim3(NB_M, 2), 256>>>(ph0, W2r, b2r, ph1, N_NODES, 128, HID, HID,            0, 1);
    k_edge_conv<<<EB, 256>>>(W2n, HID + EDGE_DIM, HID, pA, ph1);

    // layer 3
    k_linear<<<dim3(NB_M, 2), 256>>>(ph1, W3n, b3n, pA,  N_NODES, 128, HID, HID + EDGE_DIM, 0, 0);
    k_linear<<<dim3(NB_M, 2), 256>>>(ph1, W3r, b3r, ph0, N_NODES, 128, HID, HID,            0, 1);
    k_edge_conv<<<EB, 256>>>(W3n, HID + EDGE_DIM, HID, pA, ph0);
    // h3 = ph0

    // gate MLP
    k_linear<<<dim3(NB_M, 1), 256>>>(ph0, Wg1, bg1, pg1,   N_NODES, 64, 128, 128, 0, 2);
    k_linear<<<dim3(NB_M, 1), 256>>>(pg1, Wg2, bg2, pg2,   N_NODES, 32, 64,  64,  0, 2);
    k_linear<<<dim3(NB_M, 1), 256>>>(pg2, Wg3, bg3, pgate, N_NODES, 1,  32,  32,  0, 0);

    // graph segments + attention readout (att written after the [G,5] preds)
    k_gcnt <<<(N_NODES + 255) / 256, 256>>>(batch);
    k_gscan<<<1, 32>>>();
    k_attn <<<N_GRAPHS, 128>>>(ph0, out + N_GRAPHS * 5);

    // head MLP
    k_concat<<<(N_GRAPHS * 256 + 255) / 256, 256>>>(u_soap, u_dimer);
    k_linear<<<dim3(1, 4), 256>>>(pe2, Wl1, bl1, po1, N_GRAPHS, 256, 256, 256, 0, 2);
    k_linear<<<dim3(1, 2), 256>>>(po1, Wl2, bl2, po2, N_GRAPHS, 128, 256, 256, 0, 2);
    k_linear<<<dim3(1, 1), 256>>>(po2, Wl3, bl3, po3, N_GRAPHS, 64,  128, 128, 0, 2);
    k_linear<<<dim3(1, 1), 256>>>(po3, Wl,  bl,  po4, N_GRAPHS, 4,   64,  64,  0, 0);
    k_out<<<1, 128>>>(out);
}

// round 13
// speedup vs baseline: 1.8255x; 1.3287x over previous
#include <cuda_runtime.h>
#include <cuda_bf16.h>
#include <math.h>

#define N_NODES   50000
#define N_EDGES   1600000
#define N_GRAPHS  128
#define EDGE_DIM  43
#define IN_DIM    35
#define HID       128
#define NSCB      ((N_NODES + 1023) / 1024)   // 49 scan blocks

// ---------------- scratch (device globals: sanctioned scratch mechanism) ----------------
__device__ float g_attr_s[(size_t)N_EDGES * EDGE_DIM];   // sorted edge_attr (275MB)
__device__ int   g_src_s[N_EDGES];
__device__ int   g_perm[N_EDGES];
__device__ int   g_src32[N_EDGES];
__device__ int   g_deg[N_NODES];
__device__ int   g_cursor[N_NODES];
__device__ int   g_bsum[64];
__device__ int   g_boff[64];
__device__ int   g_flag_ei;      // 1 = edge_index is int64
__device__ int   g_flag_b;       // 1 = batch is int64
__device__ float g_A[(size_t)N_NODES * HID];             // per-node edge-side pre-activation
__device__ float g_hbuf[2][(size_t)N_NODES * HID];
__device__ float g_g1[(size_t)N_NODES * 64];
__device__ float g_g2[(size_t)N_NODES * 32];
__device__ float g_gate[N_NODES];
__device__ int   g_gcnt[N_GRAPHS];
__device__ int   g_gptr[N_GRAPHS + 1];
__device__ float g_emb[N_GRAPHS * HID];
__device__ float g_e2[N_GRAPHS * 256];
__device__ float g_o1[N_GRAPHS * 256];
__device__ float g_o2[N_GRAPHS * 128];
__device__ float g_o3[N_GRAPHS * 64];
__device__ float g_o4[N_GRAPHS * 4];

// ---------------- helpers ----------------
// tanh with 1 MUFU (EX2) instead of 2: reciprocal of d=1+t, d in (1,2], done on the
// FMA pipe via minimax seed + 2 Newton steps (rel err <= ~1.3e-5 worst case).
__device__ __forceinline__ float fast_tanh(float x) {
    float ax = fabsf(x);
    float t  = __expf(-2.0f * ax);            // <= 1, no overflow; 1 MUFU
    float d  = 1.0f + t;
    float r  = fmaf(-0.5f, d, 1.45711f);      // seed for 1/d on (1,2]
    r = r * fmaf(-d, r, 2.0f);                // Newton 1
    r = r * fmaf(-d, r, 2.0f);                // Newton 2
    float res = (1.0f - t) * r;
    return copysignf(res, x);
}

// ---------------- dtype probes + CSR build ----------------
__global__ void k_zero() {
    int i = blockIdx.x * blockDim.x + threadIdx.x;
    if (i < N_NODES)  g_deg[i]  = 0;
    if (i < N_GRAPHS) g_gcnt[i] = 0;
    if (i == 0) { g_flag_ei = 1; g_flag_b = 1; }
}

__global__ void k_detect_ei(const void* __restrict__ ei) {
    int e = blockIdx.x * blockDim.x + threadIdx.x;
    if (e < N_EDGES) {
        long long v = ((const long long*)ei)[e];
        if (v < 0 || v >= N_NODES) g_flag_ei = 0;
    }
}

__global__ void k_detect_b(const void* __restrict__ b) {
    int i = blockIdx.x * blockDim.x + threadIdx.x;
    if (i < N_NODES / 2) {
        long long v = ((const long long*)b)[i];
        if (v < 0 || v >= N_GRAPHS) g_flag_b = 0;
    }
}

__global__ void k_hist(const void* __restrict__ ei) {
    int e = blockIdx.x * blockDim.x + threadIdx.x;
    if (e < N_EDGES) {
        int s = g_flag_ei ? (int)((const long long*)ei)[e]
                          : ((const int*)ei)[e];
        if (s < 0) s = 0; else if (s >= N_NODES) s = N_NODES - 1;  // crash guard
        g_src32[e] = s;
        atomicAdd(&g_deg[s], 1);
    }
}

// parallel 3-phase exclusive scan of g_deg into g_cursor
__global__ void k_scan1() {
    __shared__ int sh[1024];
    int b = blockIdx.x, t = threadIdx.x;
    int i = b * 1024 + t;
    int v = (i < N_NODES) ? g_deg[i] : 0;
    sh[t] = v;
    __syncthreads();
    for (int off = 1; off < 1024; off <<= 1) {
        int add = (t >= off) ? sh[t - off] : 0;
        __syncthreads();
        sh[t] += add;
        __syncthreads();
    }
    if (i < N_NODES) g_cursor[i] = sh[t] - v;   // exclusive within block
    if (t == 1023) g_bsum[b] = sh[1023];
}
__global__ void k_scan2() {
    if (threadIdx.x == 0 && blockIdx.x == 0) {
        int run = 0;
        for (int b = 0; b < NSCB; b++) { g_boff[b] = run; run += g_bsum[b]; }
    }
}
__global__ void k_scan3() {
    int i = blockIdx.x * blockDim.x + threadIdx.x;
    if (i < N_NODES) g_cursor[i] += g_boff[i >> 10];
}

__global__ void k_scatter() {
    int e = blockIdx.x * blockDim.x + threadIdx.x;
    if (e < N_EDGES) {
        int s = g_src32[e];
        int p = atomicAdd(&g_cursor[s], 1);
        if (p >= 0 && p < N_EDGES) {    // crash guard
            g_perm[p]  = e;
            g_src_s[p] = s;
        }
    }
}

__global__ void k_permute(const float* __restrict__ attr) {
    int idx = blockIdx.x * blockDim.x + threadIdx.x;
    if (idx < N_EDGES * EDGE_DIM) {
        int p = idx / EDGE_DIM;
        int c = idx - p * EDGE_DIM;
        g_attr_s[idx] = attr[(size_t)g_perm[p] * EDGE_DIM + c];
    }
}

// ---------------- generic tiled linear: Y[M,N] = act(X[M,K] @ W[:, woff:woff+K].T + b) ----------------
// grid: (ceil(M/128), ceil(N/64)); block 256; micro-tile 8x4   (proven R5 version)
__global__ void k_linear(const float* __restrict__ X, const float* __restrict__ W,
                         const float* __restrict__ bias, float* __restrict__ Y,
                         int M, int N, int K, int ldw, int woff, int act)
{
    __shared__ __align__(16) float Xs[16][132];
    __shared__ __align__(16) float Ws[16][68];
    int tid = threadIdx.x;
    int M0 = blockIdx.x * 128;
    int N0 = blockIdx.y * 64;
    int ty = tid >> 4, tx = tid & 15;
    float acc[8][4];
#pragma unroll
    for (int i = 0; i < 8; i++)
#pragma unroll
        for (int j = 0; j < 4; j++) acc[i][j] = 0.f;

    for (int k0 = 0; k0 < K; k0 += 16) {
#pragma unroll
        for (int l = 0; l < 8; l++) {
            int idx = tid + l * 256;
            int m = idx >> 4, k = idx & 15;
            int gm = M0 + m, gk = k0 + k;
            Xs[k][m] = (gm < M && gk < K) ? X[(size_t)gm * K + gk] : 0.f;
        }
#pragma unroll
        for (int l = 0; l < 4; l++) {
            int idx = tid + l * 256;
            int n = idx >> 4, k = idx & 15;
            int gn = N0 + n, gk = k0 + k;
            Ws[k][n] = (gn < N && gk < K) ? W[gn * ldw + woff + gk] : 0.f;
        }
        __syncthreads();
#pragma unroll
        for (int kk = 0; kk < 16; kk++) {
            float4 a0 = *(const float4*)&Xs[kk][ty * 8];
            float4 a1 = *(const float4*)&Xs[kk][ty * 8 + 4];
            float4 w  = *(const float4*)&Ws[kk][tx * 4];
            float a[8] = {a0.x, a0.y, a0.z, a0.w, a1.x, a1.y, a1.z, a1.w};
            float wv[4] = {w.x, w.y, w.z, w.w};
#pragma unroll
            for (int i = 0; i < 8; i++)
#pragma unroll
                for (int j = 0; j < 4; j++) acc[i][j] += a[i] * wv[j];
        }
        __syncthreads();
    }
#pragma unroll
    for (int j = 0; j < 4; j++) {
        int gn = N0 + tx * 4 + j;
        if (gn >= N) continue;
        float b = bias[gn];
#pragma unroll
        for (int i = 0; i < 8; i++) {
            int gm = M0 + ty * 8 + i;
            if (gm >= M) continue;
            float v = acc[i][j] + b;
            if (act == 1)      v = fast_tanh(v);
            else if (act == 2) v = fmaxf(v, 0.f);
            Y[(size_t)gm * N + gn] = v;
        }
    }
}

// ---------------- fused edge GEMM + tanh + segment scatter (R5-proven layout) ----------------
// out[src[e]] += tanh(A[src[e]] + attr_sorted[e] @ We.T), 128-edge x 128-channel tile
__global__ void k_edge_conv(const float* __restrict__ W, int ldw, int woff,
                            const float* __restrict__ A, float* __restrict__ out)
{
    __shared__ __align__(16) float As[EDGE_DIM][132];   // [k][edge]
    __shared__ __align__(16) float Ws[EDGE_DIM][132];   // [k][channel]
    __shared__ int ssrc[128];
    int tid = threadIdx.x;
    int t0  = blockIdx.x * 128;
    int nE  = N_EDGES - t0; if (nE > 128) nE = 128;
    int tot = nE * EDGE_DIM;
    const float* attrBase = g_attr_s + (size_t)t0 * EDGE_DIM;   // contiguous tile
#pragma unroll
    for (int l = 0; l < 22; l++) {
        int idx = tid + l * 256;
        if (idx < tot) {
            int e = idx / EDGE_DIM;
            int k = idx - e * EDGE_DIM;
            As[k][e] = attrBase[idx];
        }
    }
#pragma unroll
    for (int l = 0; l < 22; l++) {
        int idx = tid + l * 256;
        if (idx < 128 * EDGE_DIM) {
            int c = idx / EDGE_DIM;
            int k = idx - c * EDGE_DIM;
            Ws[k][c] = W[c * ldw + woff + k];
        }
    }
    if (tid < 128) ssrc[tid] = (t0 + tid < N_EDGES) ? g_src_s[t0 + tid] : -1;
    __syncthreads();

    int ty = tid >> 4, tx = tid & 15;
    float acc[8][8];
#pragma unroll
    for (int i = 0; i < 8; i++)
#pragma unroll
        for (int j = 0; j < 8; j++) acc[i][j] = 0.f;

#pragma unroll
    for (int k = 0; k < EDGE_DIM; k++) {
        float4 a0 = *(const float4*)&As[k][ty * 8];
        float4 a1 = *(const float4*)&As[k][ty * 8 + 4];
        float4 b0 = *(const float4*)&Ws[k][tx * 8];
        float4 b1 = *(const float4*)&Ws[k][tx * 8 + 4];
        float a[8] = {a0.x, a0.y, a0.z, a0.w, a1.x, a1.y, a1.z, a1.w};
        float b[8] = {b0.x, b0.y, b0.z, b0.w, b1.x, b1.y, b1.z, b1.w};
#pragma unroll
        for (int i = 0; i < 8; i++)
#pragma unroll
            for (int j = 0; j < 8; j++) acc[i][j] += a[i] * b[j];
    }

    // epilogue: per-thread run-length segment reduce over 8 sorted edges
    float part[8], areg[8];
    int prev = -1;
#pragma unroll
    for (int i = 0; i < 8; i++) {
        int s = ssrc[ty * 8 + i];
        if (s >= 0) {
            if (s != prev) {
                if (prev >= 0) {
                    float* op = out + (size_t)prev * HID + tx * 8;
#pragma unroll
                    for (int j = 0; j < 8; j++) atomicAdd(op + j, part[j]);
                }
                prev = s;
                const float4* Ap = (const float4*)(A + (size_t)s * HID + tx * 8);
                float4 v0 = Ap[0], v1 = Ap[1];
                areg[0]=v0.x; areg[1]=v0.y; areg[2]=v0.z; areg[3]=v0.w;
                areg[4]=v1.x; areg[5]=v1.y; areg[6]=v1.z; areg[7]=v1.w;
#pragma unroll
                for (int j = 0; j < 8; j++) part[j] = 0.f;
            }
#pragma unroll
            for (int j = 0; j < 8; j++) part[j] += fast_tanh(acc[i][j] + areg[j]);
        }
    }
    if (prev >= 0) {
        float* op = out + (size_t)prev * HID + tx * 8;
#pragma unroll
        for (int j = 0; j < 8; j++) atomicAdd(op + j, part[j]);
    }
}

// ---------------- graph segmentation + attention readout ----------------
__global__ void k_gcnt(const void* __restrict__ batch) {
    int n = blockIdx.x * blockDim.x + threadIdx.x;
    if (n < N_NODES) {
        int g = g_flag_b ? (int)((const long long*)batch)[n]
                         : ((const int*)batch)[n];
        if (g < 0) g = 0; else if (g >= N_GRAPHS) g = N_GRAPHS - 1;  // crash guard
        atomicAdd(&g_gcnt[g], 1);
    }
}

__global__ void k_gscan() {
    if (threadIdx.x == 0 && blockIdx.x == 0) {
        int run = 0;
        g_gptr[0] = 0;
        for (int g = 0; g < N_GRAPHS; g++) { run += g_gcnt[g]; g_gptr[g + 1] = run; }
    }
}

// one block (128 threads) per graph: segment softmax + weighted sum
__global__ void k_attn(const float* __restrict__ h, float* __restrict__ attout) {
    int g = blockIdx.x, t = threadIdx.x;
    int lo = g_gptr[g], hi = g_gptr[g + 1];
    __shared__ float red[128];
    float m = -1e30f;
    for (int n = lo + t; n < hi; n += 128) m = fmaxf(m, g_gate[n]);
    red[t] = m; __syncthreads();
    for (int s = 64; s > 0; s >>= 1) { if (t < s) red[t] = fmaxf(red[t], red[t + s]); __syncthreads(); }
    m = red[0]; __syncthreads();
    float sum = 0.f;
    for (int n = lo + t; n < hi; n += 128) sum += __expf(g_gate[n] - m);
    red[t] = sum; __syncthreads();
    for (int s = 64; s > 0; s >>= 1) { if (t < s) red[t] += red[t + s]; __syncthreads(); }
    float inv = 1.0f / (red[0] + 1e-16f);
    for (int n = lo + t; n < hi; n += 128) attout[n] = __expf(g_gate[n] - m) * inv;
    float a0 = 0.f, a1 = 0.f, a2 = 0.f, a3 = 0.f;
    int n = lo;
    for (; n + 3 < hi; n += 4) {
        float w0 = __expf(g_gate[n]     - m) * inv;
        float w1 = __expf(g_gate[n + 1] - m) * inv;
        float w2 = __expf(g_gate[n + 2] - m) * inv;
        float w3 = __expf(g_gate[n + 3] - m) * inv;
        a0 += w0 * h[(size_t)n * HID + t];
        a1 += w1 * h[(size_t)(n + 1) * HID + t];
        a2 += w2 * h[(size_t)(n + 2) * HID + t];
        a3 += w3 * h[(size_t)(n + 3) * HID + t];
    }
    for (; n < hi; n++) {
        a0 += __expf(g_gate[n] - m) * inv * h[(size_t)n * HID + t];
    }
    g_emb[g * HID + t] = (a0 + a1) + (a2 + a3);
}

__global__ void k_concat(const float* __restrict__ us, const float* __restrict__ ud) {
    int idx = blockIdx.x * blockDim.x + threadIdx.x;
    if (idx < N_GRAPHS * 256) {
        int g = idx >> 8, c = idx & 255;
        float v;
        if (c < 128)      v = g_emb[g * 128 + c];
        else if (c < 192) v = us[g * 64 + (c - 128)];
        else              v = ud[g * 64 + (c - 192)];
        g_e2[idx] = v;
    }
}

__global__ void k_out(float* __restrict__ out) {
    int g = threadIdx.x;
    if (g < N_GRAPHS) {
        float s = 0.f;
#pragma unroll
        for (int j = 0; j < 4; j++) { float v = g_o4[g * 4 + j]; out[g * 5 + j] = v; s += v; }
        out[g * 5 + 4] = s;
    }
}

// ---------------- driver ----------------
extern "C" void kernel_launch(void* const* d_in, const int* in_sizes, int n_in,
                              void* d_out, int out_size)
{
    const float* x        = (const float*)d_in[0];
    const float* edge_attr= (const float*)d_in[1];
    const float* u_soap   = (const float*)d_in[2];
    const float* u_dimer  = (const float*)d_in[3];
    const float* W1n = (const float*)d_in[4];  const float* b1n = (const float*)d_in[5];
    const float* W1r = (const float*)d_in[6];  const float* b1r = (const float*)d_in[7];
    const float* W2n = (const float*)d_in[8];  const float* b2n = (const float*)d_in[9];
    const float* W2r = (const float*)d_in[10]; const float* b2r = (const float*)d_in[11];
    const float* W3n = (const float*)d_in[12]; const float* b3n = (const float*)d_in[13];
    const float* W3r = (const float*)d_in[14]; const float* b3r = (const float*)d_in[15];
    const float* Wg1 = (const float*)d_in[16]; const float* bg1 = (const float*)d_in[17];
    const float* Wg2 = (const float*)d_in[18]; const float* bg2 = (const float*)d_in[19];
    const float* Wg3 = (const float*)d_in[20]; const float* bg3 = (const float*)d_in[21];
    const float* Wl1 = (const float*)d_in[22]; const float* bl1 = (const float*)d_in[23];
    const float* Wl2 = (const float*)d_in[24]; const float* bl2 = (const float*)d_in[25];
    const float* Wl3 = (const float*)d_in[26]; const float* bl3 = (const float*)d_in[27];
    const float* Wl  = (const float*)d_in[28]; const float* bl  = (const float*)d_in[29];
    const void*  edge_index = d_in[30];
    const void*  batch      = d_in[31];
    float* out = (float*)d_out;

    float *pA, *ph, *pg1, *pg2, *pgate, *pe2, *po1, *po2, *po3, *po4;
    cudaGetSymbolAddress((void**)&pA,    g_A);
    cudaGetSymbolAddress((void**)&ph,    g_hbuf);
    cudaGetSymbolAddress((void**)&pg1,   g_g1);
    cudaGetSymbolAddress((void**)&pg2,   g_g2);
    cudaGetSymbolAddress((void**)&pgate, g_gate);
    cudaGetSymbolAddress((void**)&pe2,   g_e2);
    cudaGetSymbolAddress((void**)&po1,   g_o1);
    cudaGetSymbolAddress((void**)&po2,   g_o2);
    cudaGetSymbolAddress((void**)&po3,   g_o3);
    cudaGetSymbolAddress((void**)&po4,   g_o4);
    float* ph0 = ph;
    float* ph1 = ph + (size_t)N_NODES * HID;

    const int NB_M = (N_NODES + 127) / 128;            // 391
    const int EB   = (N_EDGES + 127) / 128;            // 12500

    // dtype probes + CSR build
    k_zero     <<<(N_NODES + 255) / 256, 256>>>();
    k_detect_ei<<<(N_EDGES + 255) / 256, 256>>>(edge_index);
    k_detect_b <<<(N_NODES / 2 + 255) / 256, 256>>>(batch);
    k_hist     <<<(N_EDGES + 255) / 256, 256>>>(edge_index);
    k_scan1    <<<NSCB, 1024>>>();
    k_scan2    <<<1, 32>>>();
    k_scan3    <<<(N_NODES + 255) / 256, 256>>>();
    k_scatter  <<<(N_EDGES + 255) / 256, 256>>>();
    k_permute  <<<(N_EDGES * EDGE_DIM + 255) / 256, 256>>>(edge_attr);

    // layer 1 (K = IN_DIM)
    k_linear<<<dim3(NB_M, 2), 256>>>(x,   W1n, b1n, pA,  N_NODES, 128, IN_DIM, IN_DIM + EDGE_DIM, 0, 0);
    k_linear<<<dim3(NB_M, 2), 256>>>(x,   W1r, b1r, ph0, N_NODES, 128, IN_DIM, IN_DIM,            0, 1);
    k_edge_conv<<<EB, 256>>>(W1n, IN_DIM + EDGE_DIM, IN_DIM, pA, ph0);

    // layer 2 (K = HID)
    k_linear<<<dim3(NB_M, 2), 256>>>(ph0, W2n, b2n, pA,  N_NODES, 128, HID, HID + EDGE_DIM, 0, 0);
    k_linear<<<dim3(NB_M, 2), 256>>>(ph0, W2r, b2r, ph1, N_NODES, 128, HID, HID,            0, 1);
    k_edge_conv<<<EB, 256>>>(W2n, HID + EDGE_DIM, HID, pA, ph1);

    // layer 3
    k_linear<<<dim3(NB_M, 2), 256>>>(ph1, W3n, b3n, pA,  N_NODES, 128, HID, HID + EDGE_DIM, 0, 0);
    k_linear<<<dim3(NB_M, 2), 256>>>(ph1, W3r, b3r, ph0, N_NODES, 128, HID, HID,            0, 1);
    k_edge_conv<<<EB, 256>>>(W3n, HID + EDGE_DIM, HID, pA, ph0);
    // h3 = ph0

    // gate MLP
    k_linear<<<dim3(NB_M, 1), 256>>>(ph0, Wg1, bg1, pg1,   N_NODES, 64, 128, 128, 0, 2);
    k_linear<<<dim3(NB_M, 1), 256>>>(pg1, Wg2, bg2, pg2,   N_NODES, 32, 64,  64,  0, 2);
    k_linear<<<dim3(NB_M, 1), 256>>>(pg2, Wg3, bg3, pgate, N_NODES, 1,  32,  32,  0, 0);

    // graph segments + attention readout (att written after the [G,5] preds)
    k_gcnt <<<(N_NODES + 255) / 256, 256>>>(batch);
    k_gscan<<<1, 32>>>();
    k_attn <<<N_GRAPHS, 128>>>(ph0, out + N_GRAPHS * 5);

    // head MLP
    k_concat<<<(N_GRAPHS * 256 + 255) / 256, 256>>>(u_soap, u_dimer);
    k_linear<<<dim3(1, 4), 256>>>(pe2, Wl1, bl1, po1, N_GRAPHS, 256, 256, 256, 0, 2);
    k_linear<<<dim3(1, 2), 256>>>(po1, Wl2, bl2, po2, N_GRAPHS, 128, 256, 256, 0, 2);
    k_linear<<<dim3(1, 1), 256>>>(po2, Wl3, bl3, po3, N_GRAPHS, 64,  128, 128, 0, 2);
    k_linear<<<dim3(1, 1), 256>>>(po3, Wl,  bl,  po4, N_GRAPHS, 4,   64,  64,  0, 0);
    k_out<<<1, 128>>>(out);
}